// round 12
// baseline (speedup 1.0000x reference)
#include <cuda_runtime.h>
#include <cuda_bf16.h>
#include <cstdint>

#define BATCH 8
#define SEQ   4096
#define DIM   256
#define MTOT  (BATCH * SEQ)   // 32768

// ---------------- static scratch (no allocation allowed) -------------------
__device__ __nv_bfloat16 g_xb[(size_t)MTOT * DIM];          // 16 MB  x in bf16
__device__ __nv_bfloat16 g_Wt[3 * DIM * DIM];               // 384 KB W^T bf16 [n][k]
__device__ __nv_bfloat16 g_Qb[(size_t)MTOT * DIM];          // 16 MB
__device__ __nv_bfloat16 g_Kb[(size_t)MTOT * DIM];          // 16 MB
__device__ __nv_bfloat16 g_Vb[(size_t)MTOT * DIM];          // 16 MB
__device__ __nv_bfloat16 g_P[(size_t)BATCH * SEQ * SEQ];    // 256 MB exp(scores)
__device__ float g_r[BATCH * SEQ];                          // row sums of exp
__device__ float g_a[BATCH * SEQ];                          // 1/r
__device__ float g_w[BATCH * SEQ];                          // column weights

// ---------------- helpers ---------------------------------------------------
__device__ __forceinline__ uint32_t smem_u32(const void* p) {
    return (uint32_t)__cvta_generic_to_shared(p);
}
__device__ __forceinline__ void ldsm_x4(uint32_t& r0, uint32_t& r1,
                                        uint32_t& r2, uint32_t& r3, uint32_t a) {
    asm volatile("ldmatrix.sync.aligned.m8n8.x4.shared.b16 {%0,%1,%2,%3}, [%4];"
                 : "=r"(r0), "=r"(r1), "=r"(r2), "=r"(r3) : "r"(a));
}
__device__ __forceinline__ void mma16816(float& c0, float& c1, float& c2, float& c3,
                                         uint32_t a0, uint32_t a1, uint32_t a2, uint32_t a3,
                                         uint32_t b0, uint32_t b1) {
    asm volatile(
        "mma.sync.aligned.m16n8k16.row.col.f32.bf16.bf16.f32 "
        "{%0,%1,%2,%3}, {%4,%5,%6,%7}, {%8,%9}, {%0,%1,%2,%3};"
        : "+f"(c0), "+f"(c1), "+f"(c2), "+f"(c3)
        : "r"(a0), "r"(a1), "r"(a2), "r"(a3), "r"(b0), "r"(b1));
}
#define CP_ASYNC16(s, g) \
    asm volatile("cp.async.cg.shared.global [%0], [%1], 16;" :: "r"(s), "l"(g))
#define CP_COMMIT() asm volatile("cp.async.commit_group;")
#define CP_WAIT1()  asm volatile("cp.async.wait_group 1;")
#define CP_WAIT0()  asm volatile("cp.async.wait_group 0;")

// ---------------- pipelined GEMM core ---------------------------------------
// CTA tile 128x128, K=256 contraction, k-step 32, 3-stage cp.async pipeline.
// 128 threads = 4 warps in 2(m) x 2(n); warp tile 64x64; mma m16n8k16.
// LDSM:MMA ratio 8:32 per kf (was 12:32 with 64x32 warps) -> lower LDSM floor.
#define LDPAD   40
#define STAGE_A (128 * LDPAD * 2)              // 10240 B
#define STAGE_SZ (2 * STAGE_A)                 // A + B = 20480 B
#define NSTAGE  3
#define GEMM_SMEM (NSTAGE * STAGE_SZ)          // 61440 B

// issue cp.async loads of one 128x32 chunk of A and of B into stage buffer
__device__ __forceinline__ void pipe_load(const __nv_bfloat16* __restrict__ A,
                                          const __nv_bfloat16* __restrict__ B,
                                          int m0, int n0, int k0,
                                          char* stage) {
    const int t = threadIdx.x;
#pragma unroll
    for (int j = 0; j < 4; j++) {
        const int chunk = t + j * 128;          // 0..511
        const int r   = chunk >> 2;             // row 0..127
        const int cEl = (chunk & 3) * 8;        // col elem 0,8,16,24
        const uint32_t soff = (uint32_t)(r * LDPAD + cEl) * 2;
        CP_ASYNC16(smem_u32(stage + soff),
                   (const void*)(A + (size_t)(m0 + r) * DIM + k0 + cEl));
        CP_ASYNC16(smem_u32(stage + STAGE_A + soff),
                   (const void*)(B + (size_t)(n0 + r) * DIM + k0 + cEl));
    }
}

// compute one k-step (32) from a stage buffer into acc[4][8][4]
__device__ __forceinline__ void pipe_compute(char* stage, float (&acc)[4][8][4]) {
    const __nv_bfloat16* As = (const __nv_bfloat16*)stage;
    const __nv_bfloat16* Bs = (const __nv_bfloat16*)(stage + STAGE_A);
    const int lane = threadIdx.x & 31;
    const int wid  = threadIdx.x >> 5;          // 0..3
    const int wm = wid >> 1, wn = wid & 1;

    const int a_row = wm * 64 + (lane & 7) + ((lane >> 3) & 1) * 8;
    const int a_col = ((lane >> 4) & 1) * 8;
    const int b_row = wn * 64 + (lane & 7) + ((lane >> 4) & 1) * 8;
    const int b_col = ((lane >> 3) & 1) * 8;

#pragma unroll
    for (int kf = 0; kf < 2; kf++) {
        uint32_t a[4][4];
#pragma unroll
        for (int mf = 0; mf < 4; mf++)
            ldsm_x4(a[mf][0], a[mf][1], a[mf][2], a[mf][3],
                    smem_u32(&As[(a_row + mf * 16) * LDPAD + kf * 16 + a_col]));
        uint32_t b[4][4];
#pragma unroll
        for (int nfp = 0; nfp < 4; nfp++)
            ldsm_x4(b[nfp][0], b[nfp][1], b[nfp][2], b[nfp][3],
                    smem_u32(&Bs[(b_row + nfp * 16) * LDPAD + kf * 16 + b_col]));
#pragma unroll
        for (int nf = 0; nf < 8; nf++) {
            const uint32_t b0 = b[nf >> 1][(nf & 1) * 2];
            const uint32_t b1 = b[nf >> 1][(nf & 1) * 2 + 1];
#pragma unroll
            for (int mf = 0; mf < 4; mf++)
                mma16816(acc[mf][nf][0], acc[mf][nf][1],
                         acc[mf][nf][2], acc[mf][nf][3],
                         a[mf][0], a[mf][1], a[mf][2], a[mf][3], b0, b1);
        }
    }
}

// full 128x128 @ K=256 main loop (8 k-steps), 3-stage pipeline
__device__ __forceinline__ void pipe_gemm(const __nv_bfloat16* __restrict__ A,
                                          const __nv_bfloat16* __restrict__ B,
                                          int m0, int n0, char* smem,
                                          float (&acc)[4][8][4]) {
    pipe_load(A, B, m0, n0, 0,  smem);            CP_COMMIT();
    pipe_load(A, B, m0, n0, 32, smem + STAGE_SZ); CP_COMMIT();
#pragma unroll
    for (int ks = 0; ks < 8; ks++) {
        if (ks < 7) CP_WAIT1(); else CP_WAIT0();
        __syncthreads();
        if (ks + 2 < 8) {
            pipe_load(A, B, m0, n0, (ks + 2) * 32, smem + ((ks + 2) % 3) * STAGE_SZ);
            CP_COMMIT();
        }
        pipe_compute(smem + (ks % 3) * STAGE_SZ, acc);
    }
}

// ---------------- Kernel 0a: x -> bf16 --------------------------------------
__global__ __launch_bounds__(256) void convert_x(const float* __restrict__ x) {
    const size_t i = ((size_t)blockIdx.x * 256 + threadIdx.x) * 4;
    float4 v = *(const float4*)&x[i];
    *(__nv_bfloat162*)&g_xb[i]     = __floats2bfloat162_rn(v.x, v.y);
    *(__nv_bfloat162*)&g_xb[i + 2] = __floats2bfloat162_rn(v.z, v.w);
}

// ---------------- Kernel 0b: W -> W^T bf16 ----------------------------------
__global__ void transpose_w(const float* __restrict__ Wq,
                            const float* __restrict__ Wk,
                            const float* __restrict__ Wv) {
    const float* W = (blockIdx.y == 0) ? Wq : (blockIdx.y == 1) ? Wk : Wv;
    const int n = blockIdx.x;
    const int k = threadIdx.x;
    g_Wt[blockIdx.y * DIM * DIM + n * DIM + k] = __float2bfloat16(W[k * DIM + n]);
}

// ---------------- Kernel 1: QKV projection ----------------------------------
__global__ __launch_bounds__(128, 2) void qkv_mma(const float* __restrict__ bq,
                                                  const float* __restrict__ bk,
                                                  const float* __restrict__ bv) {
    extern __shared__ char smem[];
    const int z = blockIdx.z;
    const __nv_bfloat16* B = g_Wt + z * DIM * DIM;
    const float* bias = (z == 0) ? bq : (z == 1) ? bk : bv;
    __nv_bfloat16* out = (z == 0) ? g_Qb : (z == 1) ? g_Kb : g_Vb;

    const int m0 = blockIdx.x * 128;
    const int n0 = blockIdx.y * 128;

    float acc[4][8][4] = {};
    pipe_gemm(g_xb, B, m0, n0, smem, acc);

    const int lane = threadIdx.x & 31, wid = threadIdx.x >> 5;
    const int wm = wid >> 1, wn = wid & 1;
    const int g = lane >> 2, c2 = (lane & 3) * 2;

#pragma unroll
    for (int mf = 0; mf < 4; mf++) {
        const int row = m0 + wm * 64 + mf * 16 + g;
#pragma unroll
        for (int nf = 0; nf < 8; nf++) {
            const int col = n0 + wn * 64 + nf * 8 + c2;
            const float b0v = bias[col], b1v = bias[col + 1];
            *(__nv_bfloat162*)&out[(size_t)row * DIM + col] =
                __floats2bfloat162_rn(acc[mf][nf][0] + b0v, acc[mf][nf][1] + b1v);
            *(__nv_bfloat162*)&out[(size_t)(row + 8) * DIM + col] =
                __floats2bfloat162_rn(acc[mf][nf][2] + b0v, acc[mf][nf][3] + b1v);
        }
    }
}

// ---------------- Kernel 2: P = exp(Q K^T * scale), row sums ----------------
__global__ __launch_bounds__(128, 2) void scores_mma() {
    extern __shared__ char smem[];
    const int b  = blockIdx.z;
    const int m0 = blockIdx.y * 128;   // q tile
    const int n0 = blockIdx.x * 128;   // k tile

    const __nv_bfloat16* A = g_Qb + (size_t)b * SEQ * DIM;
    const __nv_bfloat16* B = g_Kb + (size_t)b * SEQ * DIM;

    float acc[4][8][4] = {};
    pipe_gemm(A, B, m0, n0, smem, acc);

    const float scale = 0.0625f;  // 1/sqrt(256)
    __nv_bfloat16* Pb = g_P + (size_t)b * SEQ * SEQ;

    const int lane = threadIdx.x & 31, wid = threadIdx.x >> 5;
    const int wm = wid >> 1, wn = wid & 1;
    const int g = lane >> 2, c2 = (lane & 3) * 2;

#pragma unroll
    for (int mf = 0; mf < 4; mf++) {
        const int q = m0 + wm * 64 + mf * 16 + g;   // rows q, q+8
        float s0 = 0.f, s1 = 0.f;
#pragma unroll
        for (int nf = 0; nf < 8; nf++) {
            const int col = n0 + wn * 64 + nf * 8 + c2;
            float p0 = __expf(acc[mf][nf][0] * scale);
            float p1 = __expf(acc[mf][nf][1] * scale);
            float p2 = __expf(acc[mf][nf][2] * scale);
            float p3 = __expf(acc[mf][nf][3] * scale);
            __nv_bfloat162 v0 = __floats2bfloat162_rn(p0, p1);
            __nv_bfloat162 v1 = __floats2bfloat162_rn(p2, p3);
            __stcs((__nv_bfloat162*)&Pb[(size_t)q * SEQ + col],       v0);
            __stcs((__nv_bfloat162*)&Pb[(size_t)(q + 8) * SEQ + col], v1);
            s0 += p0 + p1;
            s1 += p2 + p3;
        }
        s0 += __shfl_xor_sync(0xffffffffu, s0, 1);
        s0 += __shfl_xor_sync(0xffffffffu, s0, 2);
        s1 += __shfl_xor_sync(0xffffffffu, s1, 1);
        s1 += __shfl_xor_sync(0xffffffffu, s1, 2);
        if ((lane & 3) == 0) {
            atomicAdd(&g_r[b * SEQ + q],     s0);
            atomicAdd(&g_r[b * SEQ + q + 8], s1);
        }
    }
}

// ---------------- Kernel 3a: a = 1/r ----------------------------------------
__global__ void rinv_kernel() {
    const int i = blockIdx.x * blockDim.x + threadIdx.x;
    g_a[i] = 1.0f / g_r[i];
}

// ---------------- Kernel 3b: w[k] = sum_q P[q,k] * a[q] ---------------------
// 16B loads: each thread handles 8 consecutive k columns.
__global__ __launch_bounds__(256) void colsum_kernel() {
    const int b  = blockIdx.z;
    const int q0 = blockIdx.y * 512;
    const int k  = blockIdx.x * 2048 + threadIdx.x * 8;

    const __nv_bfloat16* P = g_P + ((size_t)b * SEQ + q0) * SEQ + k;
    const float* a = g_a + b * SEQ + q0;

    float acc[8] = {};
#pragma unroll 2
    for (int q = 0; q < 512; q++) {
        const uint4 pv = __ldcs((const uint4*)(P + (size_t)q * SEQ));
        const float av = a[q];
        const __nv_bfloat162* pp = (const __nv_bfloat162*)&pv;
#pragma unroll
        for (int j = 0; j < 4; j++) {
            acc[2 * j]     += av * __bfloat162float(pp[j].x);
            acc[2 * j + 1] += av * __bfloat162float(pp[j].y);
        }
    }
#pragma unroll
    for (int j = 0; j < 8; j++)
        atomicAdd(&g_w[b * SEQ + k + j], acc[j]);
}

// ---------------- Kernel 4: out[b,h] = (1/N) sum_k w[k] V[k,h] --------------
__global__ __launch_bounds__(256) void out_kernel(float* __restrict__ out) {
    const int b = blockIdx.y;
    const int k0 = blockIdx.x * 512;
    const int h = threadIdx.x;

    const __nv_bfloat16* V = g_Vb + ((size_t)b * SEQ + k0) * DIM;
    const float* w = g_w + b * SEQ + k0;

    float acc = 0.f;
#pragma unroll 4
    for (int k = 0; k < 512; k++)
        acc += w[k] * __bfloat162float(V[(size_t)k * DIM + h]);

    atomicAdd(&out[b * DIM + h], acc * (1.0f / (float)SEQ));
}

// ---------------------------------------------------------------------------
extern "C" void kernel_launch(void* const* d_in, const int* in_sizes, int n_in,
                              void* d_out, int out_size)
{
    const float* x  = (const float*)d_in[0];
    const float* Wq = (const float*)d_in[1];
    const float* bq = (const float*)d_in[2];
    const float* Wk = (const float*)d_in[3];
    const float* bk = (const float*)d_in[4];
    const float* Wv = (const float*)d_in[5];
    const float* bv = (const float*)d_in[6];
    float* out = (float*)d_out;

    cudaFuncSetAttribute(qkv_mma,    cudaFuncAttributeMaxDynamicSharedMemorySize, GEMM_SMEM);
    cudaFuncSetAttribute(scores_mma, cudaFuncAttributeMaxDynamicSharedMemorySize, GEMM_SMEM);

    void *pr = nullptr, *pw = nullptr;
    cudaGetSymbolAddress(&pr, g_r);
    cudaGetSymbolAddress(&pw, g_w);
    cudaMemsetAsync(pr, 0, sizeof(float) * BATCH * SEQ, 0);
    cudaMemsetAsync(pw, 0, sizeof(float) * BATCH * SEQ, 0);
    cudaMemsetAsync(out, 0, sizeof(float) * BATCH * DIM, 0);

    convert_x<<<MTOT * DIM / (256 * 4), 256>>>(x);
    transpose_w<<<dim3(DIM, 3), DIM>>>(Wq, Wk, Wv);
    qkv_mma<<<dim3(MTOT / 128, DIM / 128, 3), 128, GEMM_SMEM>>>(bq, bk, bv);
    scores_mma<<<dim3(SEQ / 128, SEQ / 128, BATCH), 128, GEMM_SMEM>>>();
    rinv_kernel<<<BATCH * SEQ / 256, 256>>>();
    colsum_kernel<<<dim3(SEQ / 2048, SEQ / 512, BATCH), 256>>>();
    out_kernel<<<dim3(SEQ / 512, BATCH), 256>>>(out);
}

// round 13
// speedup vs baseline: 1.2133x; 1.2133x over previous
#include <cuda_runtime.h>
#include <cuda_bf16.h>
#include <cstdint>

#define BATCH 8
#define SEQ   4096
#define DIM   256
#define MTOT  (BATCH * SEQ)   // 32768

// ---------------- static scratch (no allocation allowed) -------------------
__device__ __nv_bfloat16 g_xb[(size_t)MTOT * DIM];          // 16 MB  x in bf16
__device__ __nv_bfloat16 g_Wt[3 * DIM * DIM];               // 384 KB W^T bf16 [n][k]
__device__ __nv_bfloat16 g_Qb[(size_t)MTOT * DIM];          // 16 MB
__device__ __nv_bfloat16 g_Kb[(size_t)MTOT * DIM];          // 16 MB
__device__ __nv_bfloat16 g_Vb[(size_t)MTOT * DIM];          // 16 MB
__device__ __nv_bfloat16 g_P[(size_t)BATCH * SEQ * SEQ];    // 256 MB exp(scores)
__device__ float g_r[BATCH * SEQ];                          // row sums of exp
__device__ float g_a[BATCH * SEQ];                          // 1/r
__device__ float g_w[BATCH * SEQ];                          // column weights

// ---------------- helpers ---------------------------------------------------
__device__ __forceinline__ uint32_t smem_u32(const void* p) {
    return (uint32_t)__cvta_generic_to_shared(p);
}
__device__ __forceinline__ void ldsm_x4(uint32_t& r0, uint32_t& r1,
                                        uint32_t& r2, uint32_t& r3, uint32_t a) {
    asm volatile("ldmatrix.sync.aligned.m8n8.x4.shared.b16 {%0,%1,%2,%3}, [%4];"
                 : "=r"(r0), "=r"(r1), "=r"(r2), "=r"(r3) : "r"(a));
}
__device__ __forceinline__ void mma16816(float& c0, float& c1, float& c2, float& c3,
                                         uint32_t a0, uint32_t a1, uint32_t a2, uint32_t a3,
                                         uint32_t b0, uint32_t b1) {
    asm volatile(
        "mma.sync.aligned.m16n8k16.row.col.f32.bf16.bf16.f32 "
        "{%0,%1,%2,%3}, {%4,%5,%6,%7}, {%8,%9}, {%0,%1,%2,%3};"
        : "+f"(c0), "+f"(c1), "+f"(c2), "+f"(c3)
        : "r"(a0), "r"(a1), "r"(a2), "r"(a3), "r"(b0), "r"(b1));
}
#define CP_ASYNC16(s, g) \
    asm volatile("cp.async.cg.shared.global [%0], [%1], 16;" :: "r"(s), "l"(g))
#define CP_COMMIT() asm volatile("cp.async.commit_group;")
#define CP_WAIT1()  asm volatile("cp.async.wait_group 1;")
#define CP_WAIT0()  asm volatile("cp.async.wait_group 0;")

// Shared tile geometry: CTA tile 128x128, K=256, k-step 32, 3 stages.
#define LDPAD   40
#define STAGE_A (128 * LDPAD * 2)              // 10240 B
#define STAGE_SZ (2 * STAGE_A)                 // A + B = 20480 B
#define NSTAGE  3
#define GEMM_SMEM (NSTAGE * STAGE_SZ)          // 61440 B

// ======================= 128-thread core (scores): 2x2 warps of 64x64 =======
__device__ __forceinline__ void pipe_load_128(const __nv_bfloat16* __restrict__ A,
                                              const __nv_bfloat16* __restrict__ B,
                                              int m0, int n0, int k0, char* stage) {
    const int t = threadIdx.x;
#pragma unroll
    for (int j = 0; j < 4; j++) {
        const int chunk = t + j * 128;
        const int r   = chunk >> 2;
        const int cEl = (chunk & 3) * 8;
        const uint32_t soff = (uint32_t)(r * LDPAD + cEl) * 2;
        CP_ASYNC16(smem_u32(stage + soff),
                   (const void*)(A + (size_t)(m0 + r) * DIM + k0 + cEl));
        CP_ASYNC16(smem_u32(stage + STAGE_A + soff),
                   (const void*)(B + (size_t)(n0 + r) * DIM + k0 + cEl));
    }
}

__device__ __forceinline__ void pipe_compute_128(char* stage, float (&acc)[4][8][4]) {
    const __nv_bfloat16* As = (const __nv_bfloat16*)stage;
    const __nv_bfloat16* Bs = (const __nv_bfloat16*)(stage + STAGE_A);
    const int lane = threadIdx.x & 31;
    const int wid  = threadIdx.x >> 5;          // 0..3
    const int wm = wid >> 1, wn = wid & 1;

    const int a_row = wm * 64 + (lane & 7) + ((lane >> 3) & 1) * 8;
    const int a_col = ((lane >> 4) & 1) * 8;
    const int b_row = wn * 64 + (lane & 7) + ((lane >> 4) & 1) * 8;
    const int b_col = ((lane >> 3) & 1) * 8;

#pragma unroll
    for (int kf = 0; kf < 2; kf++) {
        uint32_t a[4][4];
#pragma unroll
        for (int mf = 0; mf < 4; mf++)
            ldsm_x4(a[mf][0], a[mf][1], a[mf][2], a[mf][3],
                    smem_u32(&As[(a_row + mf * 16) * LDPAD + kf * 16 + a_col]));
        uint32_t b[4][4];
#pragma unroll
        for (int nfp = 0; nfp < 4; nfp++)
            ldsm_x4(b[nfp][0], b[nfp][1], b[nfp][2], b[nfp][3],
                    smem_u32(&Bs[(b_row + nfp * 16) * LDPAD + kf * 16 + b_col]));
#pragma unroll
        for (int nf = 0; nf < 8; nf++) {
            const uint32_t b0 = b[nf >> 1][(nf & 1) * 2];
            const uint32_t b1 = b[nf >> 1][(nf & 1) * 2 + 1];
#pragma unroll
            for (int mf = 0; mf < 4; mf++)
                mma16816(acc[mf][nf][0], acc[mf][nf][1],
                         acc[mf][nf][2], acc[mf][nf][3],
                         a[mf][0], a[mf][1], a[mf][2], a[mf][3], b0, b1);
        }
    }
}

__device__ __forceinline__ void pipe_gemm_128(const __nv_bfloat16* __restrict__ A,
                                              const __nv_bfloat16* __restrict__ B,
                                              int m0, int n0, char* smem,
                                              float (&acc)[4][8][4]) {
    pipe_load_128(A, B, m0, n0, 0,  smem);            CP_COMMIT();
    pipe_load_128(A, B, m0, n0, 32, smem + STAGE_SZ); CP_COMMIT();
#pragma unroll
    for (int ks = 0; ks < 8; ks++) {
        if (ks < 7) CP_WAIT1(); else CP_WAIT0();
        __syncthreads();
        if (ks + 2 < 8) {
            pipe_load_128(A, B, m0, n0, (ks + 2) * 32, smem + ((ks + 2) % 3) * STAGE_SZ);
            CP_COMMIT();
        }
        pipe_compute_128(smem + (ks % 3) * STAGE_SZ, acc);
    }
}

// ======================= 256-thread core (qkv): 2x4 warps of 64x32 ==========
__device__ __forceinline__ void pipe_load_256(const __nv_bfloat16* __restrict__ A,
                                              const __nv_bfloat16* __restrict__ B,
                                              int m0, int n0, int k0, char* stage) {
    const int t = threadIdx.x;
#pragma unroll
    for (int j = 0; j < 2; j++) {
        const int chunk = t + j * 256;
        const int r   = chunk >> 2;
        const int cEl = (chunk & 3) * 8;
        const uint32_t soff = (uint32_t)(r * LDPAD + cEl) * 2;
        CP_ASYNC16(smem_u32(stage + soff),
                   (const void*)(A + (size_t)(m0 + r) * DIM + k0 + cEl));
        CP_ASYNC16(smem_u32(stage + STAGE_A + soff),
                   (const void*)(B + (size_t)(n0 + r) * DIM + k0 + cEl));
    }
}

__device__ __forceinline__ void pipe_compute_256(char* stage, float (&acc)[4][4][4]) {
    const __nv_bfloat16* As = (const __nv_bfloat16*)stage;
    const __nv_bfloat16* Bs = (const __nv_bfloat16*)(stage + STAGE_A);
    const int lane = threadIdx.x & 31;
    const int wid  = threadIdx.x >> 5;
    const int wm = wid >> 2, wn = wid & 3;

    const int a_row = wm * 64 + (lane & 7) + ((lane >> 3) & 1) * 8;
    const int a_col = ((lane >> 4) & 1) * 8;
    const int b_row = wn * 32 + (lane & 7) + ((lane >> 4) & 1) * 8;
    const int b_col = ((lane >> 3) & 1) * 8;

#pragma unroll
    for (int kf = 0; kf < 2; kf++) {
        uint32_t a[4][4];
#pragma unroll
        for (int mf = 0; mf < 4; mf++)
            ldsm_x4(a[mf][0], a[mf][1], a[mf][2], a[mf][3],
                    smem_u32(&As[(a_row + mf * 16) * LDPAD + kf * 16 + a_col]));
        uint32_t b[2][4];
#pragma unroll
        for (int nfp = 0; nfp < 2; nfp++)
            ldsm_x4(b[nfp][0], b[nfp][1], b[nfp][2], b[nfp][3],
                    smem_u32(&Bs[(b_row + nfp * 16) * LDPAD + kf * 16 + b_col]));
#pragma unroll
        for (int nf = 0; nf < 4; nf++) {
            const uint32_t b0 = b[nf >> 1][(nf & 1) * 2];
            const uint32_t b1 = b[nf >> 1][(nf & 1) * 2 + 1];
#pragma unroll
            for (int mf = 0; mf < 4; mf++)
                mma16816(acc[mf][nf][0], acc[mf][nf][1],
                         acc[mf][nf][2], acc[mf][nf][3],
                         a[mf][0], a[mf][1], a[mf][2], a[mf][3], b0, b1);
        }
    }
}

__device__ __forceinline__ void pipe_gemm_256(const __nv_bfloat16* __restrict__ A,
                                              const __nv_bfloat16* __restrict__ B,
                                              int m0, int n0, char* smem,
                                              float (&acc)[4][4][4]) {
    pipe_load_256(A, B, m0, n0, 0,  smem);            CP_COMMIT();
    pipe_load_256(A, B, m0, n0, 32, smem + STAGE_SZ); CP_COMMIT();
#pragma unroll
    for (int ks = 0; ks < 8; ks++) {
        if (ks < 7) CP_WAIT1(); else CP_WAIT0();
        __syncthreads();
        if (ks + 2 < 8) {
            pipe_load_256(A, B, m0, n0, (ks + 2) * 32, smem + ((ks + 2) % 3) * STAGE_SZ);
            CP_COMMIT();
        }
        pipe_compute_256(smem + (ks % 3) * STAGE_SZ, acc);
    }
}

// ---------------- Kernel 0a: x -> bf16 --------------------------------------
__global__ __launch_bounds__(256) void convert_x(const float* __restrict__ x) {
    const size_t i = ((size_t)blockIdx.x * 256 + threadIdx.x) * 4;
    float4 v = *(const float4*)&x[i];
    *(__nv_bfloat162*)&g_xb[i]     = __floats2bfloat162_rn(v.x, v.y);
    *(__nv_bfloat162*)&g_xb[i + 2] = __floats2bfloat162_rn(v.z, v.w);
}

// ---------------- Kernel 0b: W -> W^T bf16 ----------------------------------
__global__ void transpose_w(const float* __restrict__ Wq,
                            const float* __restrict__ Wk,
                            const float* __restrict__ Wv) {
    const float* W = (blockIdx.y == 0) ? Wq : (blockIdx.y == 1) ? Wk : Wv;
    const int n = blockIdx.x;
    const int k = threadIdx.x;
    g_Wt[blockIdx.y * DIM * DIM + n * DIM + k] = __float2bfloat16(W[k * DIM + n]);
}

// ---------------- Kernel 1: QKV projection (256 thr, 64x32 warps) -----------
__global__ __launch_bounds__(256, 2) void qkv_mma(const float* __restrict__ bq,
                                                  const float* __restrict__ bk,
                                                  const float* __restrict__ bv) {
    extern __shared__ char smem[];
    const int z = blockIdx.z;
    const __nv_bfloat16* B = g_Wt + z * DIM * DIM;
    const float* bias = (z == 0) ? bq : (z == 1) ? bk : bv;
    __nv_bfloat16* out = (z == 0) ? g_Qb : (z == 1) ? g_Kb : g_Vb;

    const int m0 = blockIdx.x * 128;
    const int n0 = blockIdx.y * 128;

    float acc[4][4][4] = {};
    pipe_gemm_256(g_xb, B, m0, n0, smem, acc);

    const int lane = threadIdx.x & 31, wid = threadIdx.x >> 5;
    const int wm = wid >> 2, wn = wid & 3;
    const int g = lane >> 2, c2 = (lane & 3) * 2;

#pragma unroll
    for (int mf = 0; mf < 4; mf++) {
        const int row = m0 + wm * 64 + mf * 16 + g;
#pragma unroll
        for (int nf = 0; nf < 4; nf++) {
            const int col = n0 + wn * 32 + nf * 8 + c2;
            const float b0v = bias[col], b1v = bias[col + 1];
            *(__nv_bfloat162*)&out[(size_t)row * DIM + col] =
                __floats2bfloat162_rn(acc[mf][nf][0] + b0v, acc[mf][nf][1] + b1v);
            *(__nv_bfloat162*)&out[(size_t)(row + 8) * DIM + col] =
                __floats2bfloat162_rn(acc[mf][nf][2] + b0v, acc[mf][nf][3] + b1v);
        }
    }
}

// ---------------- Kernel 2: scores (128 thr, 64x64 warps) -------------------
__global__ __launch_bounds__(128, 2) void scores_mma() {
    extern __shared__ char smem[];
    const int b  = blockIdx.z;
    const int m0 = blockIdx.y * 128;   // q tile
    const int n0 = blockIdx.x * 128;   // k tile

    const __nv_bfloat16* A = g_Qb + (size_t)b * SEQ * DIM;
    const __nv_bfloat16* B = g_Kb + (size_t)b * SEQ * DIM;

    float acc[4][8][4] = {};
    pipe_gemm_128(A, B, m0, n0, smem, acc);

    const float scale = 0.0625f;  // 1/sqrt(256)
    __nv_bfloat16* Pb = g_P + (size_t)b * SEQ * SEQ;

    const int lane = threadIdx.x & 31, wid = threadIdx.x >> 5;
    const int wm = wid >> 1, wn = wid & 1;
    const int g = lane >> 2, c2 = (lane & 3) * 2;

#pragma unroll
    for (int mf = 0; mf < 4; mf++) {
        const int q = m0 + wm * 64 + mf * 16 + g;   // rows q, q+8
        float s0 = 0.f, s1 = 0.f;
#pragma unroll
        for (int nf = 0; nf < 8; nf++) {
            const int col = n0 + wn * 64 + nf * 8 + c2;
            float p0 = __expf(acc[mf][nf][0] * scale);
            float p1 = __expf(acc[mf][nf][1] * scale);
            float p2 = __expf(acc[mf][nf][2] * scale);
            float p3 = __expf(acc[mf][nf][3] * scale);
            __nv_bfloat162 v0 = __floats2bfloat162_rn(p0, p1);
            __nv_bfloat162 v1 = __floats2bfloat162_rn(p2, p3);
            __stcs((__nv_bfloat162*)&Pb[(size_t)q * SEQ + col],       v0);
            __stcs((__nv_bfloat162*)&Pb[(size_t)(q + 8) * SEQ + col], v1);
            s0 += p0 + p1;
            s1 += p2 + p3;
        }
        s0 += __shfl_xor_sync(0xffffffffu, s0, 1);
        s0 += __shfl_xor_sync(0xffffffffu, s0, 2);
        s1 += __shfl_xor_sync(0xffffffffu, s1, 1);
        s1 += __shfl_xor_sync(0xffffffffu, s1, 2);
        if ((lane & 3) == 0) {
            atomicAdd(&g_r[b * SEQ + q],     s0);
            atomicAdd(&g_r[b * SEQ + q + 8], s1);
        }
    }
}

// ---------------- Kernel 3a: a = 1/r ----------------------------------------
__global__ void rinv_kernel() {
    const int i = blockIdx.x * blockDim.x + threadIdx.x;
    g_a[i] = 1.0f / g_r[i];
}

// ---------------- Kernel 3b: w[k] = sum_q P[q,k] * a[q] ---------------------
// 16B loads, q-chunks of 128 -> grid (2, 32, 8) = 512 CTAs (3.5 waves).
__global__ __launch_bounds__(256) void colsum_kernel() {
    const int b  = blockIdx.z;
    const int q0 = blockIdx.y * 128;
    const int k  = blockIdx.x * 2048 + threadIdx.x * 8;

    const __nv_bfloat16* P = g_P + ((size_t)b * SEQ + q0) * SEQ + k;
    const float* a = g_a + b * SEQ + q0;

    float acc[8] = {};
#pragma unroll 2
    for (int q = 0; q < 128; q++) {
        const uint4 pv = __ldcs((const uint4*)(P + (size_t)q * SEQ));
        const float av = a[q];
        const __nv_bfloat162* pp = (const __nv_bfloat162*)&pv;
#pragma unroll
        for (int j = 0; j < 4; j++) {
            acc[2 * j]     += av * __bfloat162float(pp[j].x);
            acc[2 * j + 1] += av * __bfloat162float(pp[j].y);
        }
    }
#pragma unroll
    for (int j = 0; j < 8; j++)
        atomicAdd(&g_w[b * SEQ + k + j], acc[j]);
}

// ---------------- Kernel 4: out[b,h] = (1/N) sum_k w[k] V[k,h] --------------
__global__ __launch_bounds__(256) void out_kernel(float* __restrict__ out) {
    const int b = blockIdx.y;
    const int k0 = blockIdx.x * 512;
    const int h = threadIdx.x;

    const __nv_bfloat16* V = g_Vb + ((size_t)b * SEQ + k0) * DIM;
    const float* w = g_w + b * SEQ + k0;

    float acc = 0.f;
#pragma unroll 4
    for (int k = 0; k < 512; k++)
        acc += w[k] * __bfloat162float(V[(size_t)k * DIM + h]);

    atomicAdd(&out[b * DIM + h], acc * (1.0f / (float)SEQ));
}

// ---------------------------------------------------------------------------
extern "C" void kernel_launch(void* const* d_in, const int* in_sizes, int n_in,
                              void* d_out, int out_size)
{
    const float* x  = (const float*)d_in[0];
    const float* Wq = (const float*)d_in[1];
    const float* bq = (const float*)d_in[2];
    const float* Wk = (const float*)d_in[3];
    const float* bk = (const float*)d_in[4];
    const float* Wv = (const float*)d_in[5];
    const float* bv = (const float*)d_in[6];
    float* out = (float*)d_out;

    cudaFuncSetAttribute(qkv_mma,    cudaFuncAttributeMaxDynamicSharedMemorySize, GEMM_SMEM);
    cudaFuncSetAttribute(scores_mma, cudaFuncAttributeMaxDynamicSharedMemorySize, GEMM_SMEM);

    void *pr = nullptr, *pw = nullptr;
    cudaGetSymbolAddress(&pr, g_r);
    cudaGetSymbolAddress(&pw, g_w);
    cudaMemsetAsync(pr, 0, sizeof(float) * BATCH * SEQ, 0);
    cudaMemsetAsync(pw, 0, sizeof(float) * BATCH * SEQ, 0);
    cudaMemsetAsync(out, 0, sizeof(float) * BATCH * DIM, 0);

    convert_x<<<MTOT * DIM / (256 * 4), 256>>>(x);
    transpose_w<<<dim3(DIM, 3), DIM>>>(Wq, Wk, Wv);
    qkv_mma<<<dim3(MTOT / 128, DIM / 128, 3), 256, GEMM_SMEM>>>(bq, bk, bv);
    scores_mma<<<dim3(SEQ / 128, SEQ / 128, BATCH), 128, GEMM_SMEM>>>();
    rinv_kernel<<<BATCH * SEQ / 256, 256>>>();
    colsum_kernel<<<dim3(SEQ / 2048, SEQ / 128, BATCH), 256>>>();
    out_kernel<<<dim3(SEQ / 512, BATCH), 256>>>(out);
}